// round 1
// baseline (speedup 1.0000x reference)
#include <cuda_runtime.h>
#include <math.h>

#define NPTS 8192
#define NGRID 32768
#define KNN 16
#define CHUNK 2048

// ---------------- device scratch (no allocation allowed) ----------------
__device__ float4 g_pts4[NPTS];              // scaled points + |r|^2
__device__ float2 g_P[NPTS * 32];            // P[n][64] = feat[n] @ ew1[:32] + eb1  (float2-packed)
__device__ int    g_idx[NGRID * KNN];        // knn indices

// ---------------- helpers ----------------
__device__ __forceinline__ float gelu_tanh(float x) {
    // jax.nn.gelu(approximate=True): 0.5*x*(1+tanh(sqrt(2/pi)*(x+0.044715 x^3)))
    float x3 = x * x * x;
    float u = 0.7978845608028654f * fmaf(0.044715f, x3, x);
    float t = tanhf(u);
    return 0.5f * x * (1.0f + t);
}

__device__ __forceinline__ float warp_sum(float v) {
    #pragma unroll
    for (int o = 16; o; o >>= 1) v += __shfl_xor_sync(0xffffffffu, v, o);
    return v;
}

// ---------------- kernel 1: scaled points ----------------
__global__ void prep_pts_kernel(const float* __restrict__ verts) {
    int n = blockIdx.x * blockDim.x + threadIdx.x;
    if (n < NPTS) {
        float x = verts[3 * n + 0] * 32.0f;
        float y = verts[3 * n + 1] * 32.0f;
        float z = verts[3 * n + 2] * 32.0f;
        g_pts4[n] = make_float4(x, y, z, fmaf(x, x, fmaf(y, y, z * z)));
    }
}

// ---------------- kernel 2: P[n][c] = eb1[c] + sum_j feat[n][j]*ew1[j][c] ----------------
__global__ void prep_P_kernel(const float* __restrict__ feat,
                              const float* __restrict__ ew1,
                              const float* __restrict__ eb1) {
    int t = blockIdx.x * blockDim.x + threadIdx.x;   // 8192*64 threads
    int n = t >> 6, c = t & 63;
    const float* f = feat + n * 32;
    float acc = eb1[c];
    #pragma unroll
    for (int j = 0; j < 32; j++) acc = fmaf(f[j], ew1[j * 64 + c], acc);
    reinterpret_cast<float*>(g_P)[t] = acc;
}

// ---------------- kernel 3: brute-force exact KNN (matches reference d2 formula) ----------------
__global__ void __launch_bounds__(32) knn_kernel(const float* __restrict__ grid) {
    __shared__ float4 sp[CHUNK];
    int lane = threadIdx.x;
    int m = blockIdx.x * 32 + lane;      // adjacent m within a warp -> correlated inserts
    float gx = grid[3 * m + 0] * 32.0f;
    float gy = grid[3 * m + 1] * 32.0f;
    float gz = grid[3 * m + 2] * 32.0f;
    float q2 = fmaf(gx, gx, fmaf(gy, gy, gz * gz));

    float bd[KNN];
    int   bi[KNN];
    #pragma unroll
    for (int j = 0; j < KNN; j++) { bd[j] = 3.4e38f; bi[j] = 0; }

    for (int base = 0; base < NPTS; base += CHUNK) {
        #pragma unroll
        for (int i = 0; i < CHUNK / 32; i++)
            sp[lane + 32 * i] = g_pts4[base + lane + 32 * i];
        __syncwarp();
        #pragma unroll 8
        for (int i = 0; i < CHUNK; i++) {
            float4 p = sp[i];
            float dot = fmaf(gx, p.x, fmaf(gy, p.y, gz * p.z));
            float d2 = fmaf(-2.0f, dot, q2 + p.w);   // (q2 + r2) - 2*dot, like reference
            if (d2 < bd[KNN - 1]) {
                float cd = d2; int ci = base + i;
                #pragma unroll
                for (int j = 0; j < KNN; j++) {
                    bool sw = cd < bd[j];
                    float tf = bd[j]; int ti = bi[j];
                    if (sw) { bd[j] = cd; bi[j] = ti >= 0 ? ci : ci; bi[j] = ci; cd = tf; ci = ti; }
                }
            }
        }
        __syncwarp();
    }
    #pragma unroll
    for (int j = 0; j < KNN; j++) g_idx[m * KNN + j] = bi[j];
}

// ---------------- kernel 4: fused edge MLP + mean + out MLP ----------------
// warp per grid vertex; lane owns channels c0=2*lane, c1=2*lane+1
#define SM_EW2 0
#define SM_OW1 4096
#define SM_OW2 14336
#define SM_BUF 18432
#define BUF_PER_WARP 224     // 64 tmp + 160 obuf
#define EDGE_SMEM_FLOATS (SM_BUF + 8 * BUF_PER_WARP)

__global__ void __launch_bounds__(256) edge_out_kernel(
    const float* __restrict__ verts, const float* __restrict__ grid,
    const float* __restrict__ gfeat,
    const float* __restrict__ p_ew1,
    const float* __restrict__ p_eg1, const float* __restrict__ p_ebt1,
    const float* __restrict__ p_ew2, const float* __restrict__ p_eb2,
    const float* __restrict__ p_ow1, const float* __restrict__ p_ob1,
    const float* __restrict__ p_og1, const float* __restrict__ p_obt1,
    const float* __restrict__ p_ow2, const float* __restrict__ p_ob2,
    float* __restrict__ out)
{
    extern __shared__ float sm[];
    float* s_ew2 = sm + SM_EW2;
    float* s_ow1 = sm + SM_OW1;
    float* s_ow2 = sm + SM_OW2;

    int tid = threadIdx.x;
    for (int i = tid; i < 4096; i += 256)  s_ew2[i] = p_ew2[i];
    for (int i = tid; i < 10240; i += 256) s_ow1[i] = p_ow1[i];
    for (int i = tid; i < 4096; i += 256)  s_ow2[i] = p_ow2[i];
    __syncthreads();

    int warp = tid >> 5, lane = tid & 31;
    int m = blockIdx.x * 8 + warp;
    int c0 = 2 * lane, c1 = c0 + 1;
    float* tbuf = sm + SM_BUF + warp * BUF_PER_WARP;  // 64
    float* obuf = tbuf + 64;                           // 160

    // per-lane constants
    float wpx0 = p_ew1[32 * 64 + c0], wpx1 = p_ew1[32 * 64 + c1];
    float wpy0 = p_ew1[33 * 64 + c0], wpy1 = p_ew1[33 * 64 + c1];
    float wpz0 = p_ew1[34 * 64 + c0], wpz1 = p_ew1[34 * 64 + c1];
    float ceg0 = p_eg1[c0],  ceg1 = p_eg1[c1];
    float cbt0 = p_ebt1[c0], cbt1 = p_ebt1[c1];
    float cb2_0 = p_eb2[c0], cb2_1 = p_eb2[c1];
    float cob1_0 = p_ob1[c0], cob1_1 = p_ob1[c1];
    float cog0 = p_og1[c0],  cog1 = p_og1[c1];
    float cobt0 = p_obt1[c0], cobt1 = p_obt1[c1];
    float cob2_0 = p_ob2[c0], cob2_1 = p_ob2[c1];

    float gx = grid[3 * m + 0], gy = grid[3 * m + 1], gz = grid[3 * m + 2];

    float acc0 = 0.0f, acc1 = 0.0f;
    #pragma unroll 1
    for (int k = 0; k < KNN; k++) {
        int n = g_idx[m * KNN + k];
        float vx = verts[3 * n + 0], vy = verts[3 * n + 1], vz = verts[3 * n + 2];
        float rx = vx - gx, ry = vy - gy, rz = vz - gz;
        float2 Pv = g_P[n * 32 + lane];
        float h0 = fmaf(rx, wpx0, fmaf(ry, wpy0, fmaf(rz, wpz0, Pv.x)));
        float h1 = fmaf(rx, wpx1, fmaf(ry, wpy1, fmaf(rz, wpz1, Pv.y)));
        // layernorm over 64 channels (warp-wide)
        float mean = warp_sum(h0 + h1) * 0.015625f;
        float d0 = h0 - mean, d1 = h1 - mean;
        float var = warp_sum(fmaf(d0, d0, d1 * d1)) * 0.015625f;
        float rstd = rsqrtf(var + 1e-5f);
        float y0 = fmaf(d0 * rstd, ceg0, cbt0);
        float y1 = fmaf(d1 * rstd, ceg1, cbt1);
        acc0 += gelu_tanh(y0);
        acc1 += gelu_tanh(y1);
    }
    acc0 *= 0.0625f; acc1 *= 0.0625f;    // mean over K (ew2 hoisted out by linearity)

    tbuf[c0] = acc0; tbuf[c1] = acc1;
    __syncwarp();
    // agg = mean(gelu) @ ew2 + eb2
    float a0 = cb2_0, a1 = cb2_1;
    #pragma unroll 16
    for (int j = 0; j < 64; j++) {
        float gj = tbuf[j];
        float2 w = *reinterpret_cast<const float2*>(&s_ew2[j * 64 + c0]);
        a0 = fmaf(gj, w.x, a0); a1 = fmaf(gj, w.y, a1);
    }
    __syncwarp();
    obuf[c0] = a0; obuf[c1] = a1;
    obuf[64 + lane]  = gfeat[m * 96 + lane];
    obuf[96 + lane]  = gfeat[m * 96 + 32 + lane];
    obuf[128 + lane] = gfeat[m * 96 + 64 + lane];
    __syncwarp();
    // z = o @ ow1 + ob1
    float z0 = cob1_0, z1 = cob1_1;
    #pragma unroll 16
    for (int j = 0; j < 160; j++) {
        float oj = obuf[j];
        float2 w = *reinterpret_cast<const float2*>(&s_ow1[j * 64 + c0]);
        z0 = fmaf(oj, w.x, z0); z1 = fmaf(oj, w.y, z1);
    }
    // LN + gelu
    {
        float mean = warp_sum(z0 + z1) * 0.015625f;
        float d0 = z0 - mean, d1 = z1 - mean;
        float var = warp_sum(fmaf(d0, d0, d1 * d1)) * 0.015625f;
        float rstd = rsqrtf(var + 1e-5f);
        z0 = gelu_tanh(fmaf(d0 * rstd, cog0, cobt0));
        z1 = gelu_tanh(fmaf(d1 * rstd, cog1, cobt1));
    }
    __syncwarp();
    tbuf[c0] = z0; tbuf[c1] = z1;
    __syncwarp();
    // out = y @ ow2 + ob2
    float o0 = cob2_0, o1 = cob2_1;
    #pragma unroll 16
    for (int j = 0; j < 64; j++) {
        float yj = tbuf[j];
        float2 w = *reinterpret_cast<const float2*>(&s_ow2[j * 64 + c0]);
        o0 = fmaf(yj, w.x, o0); o1 = fmaf(yj, w.y, o1);
    }
    *reinterpret_cast<float2*>(&out[m * 64 + c0]) = make_float2(o0, o1);
}

// ---------------- launch ----------------
extern "C" void kernel_launch(void* const* d_in, const int* in_sizes, int n_in,
                              void* d_out, int out_size) {
    const float* verts = (const float*)d_in[0];
    const float* feat  = (const float*)d_in[1];
    const float* grid  = (const float*)d_in[2];
    const float* gfeat = (const float*)d_in[3];
    const float* ew1   = (const float*)d_in[4];
    const float* eb1   = (const float*)d_in[5];
    const float* eg1   = (const float*)d_in[6];
    const float* ebt1  = (const float*)d_in[7];
    const float* ew2   = (const float*)d_in[8];
    const float* eb2   = (const float*)d_in[9];
    const float* ow1   = (const float*)d_in[10];
    const float* ob1   = (const float*)d_in[11];
    const float* og1   = (const float*)d_in[12];
    const float* obt1  = (const float*)d_in[13];
    const float* ow2   = (const float*)d_in[14];
    const float* ob2   = (const float*)d_in[15];
    float* out = (float*)d_out;

    prep_pts_kernel<<<32, 256>>>(verts);
    prep_P_kernel<<<(NPTS * 64) / 256, 256>>>(feat, ew1, eb1);
    knn_kernel<<<NGRID / 32, 32>>>(grid);

    int smem = EDGE_SMEM_FLOATS * (int)sizeof(float);
    cudaFuncSetAttribute(edge_out_kernel, cudaFuncAttributeMaxDynamicSharedMemorySize, smem);
    edge_out_kernel<<<NGRID / 8, 256, smem>>>(verts, grid, gfeat,
                                              ew1, eg1, ebt1, ew2, eb2,
                                              ow1, ob1, og1, obt1, ow2, ob2, out);
}

// round 3
// speedup vs baseline: 1.6952x; 1.6952x over previous
#include <cuda_runtime.h>
#include <math.h>

#define NPTS 8192
#define NGRID 32768
#define KNN 16
#define KCHUNK 2048

// ---------------- device scratch ----------------
__device__ float4 g_pts4[NPTS];          // x,y,z, 0.5*|r|^2
__device__ float2 g_P[NPTS * 32];        // P[n][64] = feat@ew1[:32] + eb1
__device__ float4 g_SA[NPTS];            // S1, S2, T0, T1
__device__ float  g_T2[NPTS];
__device__ float  g_wc[9];               // Wsx,Wsy,Wsz, Mxx,Myy,Mzz, Mxy,Mxz,Myz
__device__ int    g_idx[NGRID * KNN];

// ---------------- helpers ----------------
__device__ __forceinline__ float gelu_tanh(float x) {
    float x3 = x * x * x;
    float u = 0.7978845608028654f * fmaf(0.044715f, x3, x);
    return 0.5f * x * (1.0f + tanhf(u));
}
__device__ __forceinline__ float warp_sum(float v) {
    #pragma unroll
    for (int o = 16; o; o >>= 1) v += __shfl_xor_sync(0xffffffffu, v, o);
    return v;
}

// ---------------- prep: points ----------------
__global__ void prep_pts_kernel(const float* __restrict__ verts) {
    int n = blockIdx.x * blockDim.x + threadIdx.x;
    if (n < NPTS) {
        float x = verts[3 * n], y = verts[3 * n + 1], z = verts[3 * n + 2];
        g_pts4[n] = make_float4(x, y, z, 0.5f * fmaf(x, x, fmaf(y, y, z * z)));
    }
}

// ---------------- prep: W-derived constants (1 warp) ----------------
__global__ void prep_const_kernel(const float* __restrict__ ew1) {
    int lane = threadIdx.x;
    int c0 = 2 * lane, c1 = c0 + 1;
    float wx0 = ew1[2048 + c0], wx1 = ew1[2048 + c1];
    float wy0 = ew1[2112 + c0], wy1 = ew1[2112 + c1];
    float wz0 = ew1[2176 + c0], wz1 = ew1[2176 + c1];
    float r[9];
    r[0] = warp_sum(wx0 + wx1);
    r[1] = warp_sum(wy0 + wy1);
    r[2] = warp_sum(wz0 + wz1);
    r[3] = warp_sum(fmaf(wx0, wx0, wx1 * wx1));
    r[4] = warp_sum(fmaf(wy0, wy0, wy1 * wy1));
    r[5] = warp_sum(fmaf(wz0, wz0, wz1 * wz1));
    r[6] = warp_sum(fmaf(wx0, wy0, wx1 * wy1));
    r[7] = warp_sum(fmaf(wx0, wz0, wx1 * wz1));
    r[8] = warp_sum(fmaf(wy0, wz0, wy1 * wz1));
    if (lane == 0) {
        #pragma unroll
        for (int i = 0; i < 9; i++) g_wc[i] = r[i];
    }
}

// ---------------- prep: P + per-point LN scalars (warp per point) ----------------
__global__ void prep_P_kernel(const float* __restrict__ feat,
                              const float* __restrict__ ew1,
                              const float* __restrict__ eb1) {
    int warp = threadIdx.x >> 5, lane = threadIdx.x & 31;
    int n = blockIdx.x * 8 + warp;
    int c0 = 2 * lane;
    float p0 = eb1[c0], p1 = eb1[c0 + 1];
    const float* f = feat + n * 32;
    #pragma unroll
    for (int j = 0; j < 32; j++) {
        float fj = f[j];
        float2 w = *reinterpret_cast<const float2*>(&ew1[j * 64 + c0]);
        p0 = fmaf(fj, w.x, p0); p1 = fmaf(fj, w.y, p1);
    }
    g_P[n * 32 + lane] = make_float2(p0, p1);
    float wx0 = ew1[2048 + c0], wx1 = ew1[2048 + c0 + 1];
    float wy0 = ew1[2112 + c0], wy1 = ew1[2112 + c0 + 1];
    float wz0 = ew1[2176 + c0], wz1 = ew1[2176 + c0 + 1];
    float S1 = warp_sum(p0 + p1);
    float S2 = warp_sum(fmaf(p0, p0, p1 * p1));
    float T0 = warp_sum(fmaf(p0, wx0, p1 * wx1));
    float T1 = warp_sum(fmaf(p0, wy0, p1 * wy1));
    float T2 = warp_sum(fmaf(p0, wz0, p1 * wz1));
    if (lane == 0) { g_SA[n] = make_float4(S1, S2, T0, T1); g_T2[n] = T2; }
}

// ---------------- KNN: thread-per-vertex, keep 16 largest scores ----------------
__global__ void __launch_bounds__(128) knn_kernel(const float* __restrict__ grid) {
    __shared__ float4 sp[KCHUNK];
    int tid = threadIdx.x;
    int m = blockIdx.x * 128 + tid;
    float gx = grid[3 * m], gy = grid[3 * m + 1], gz = grid[3 * m + 2];

    float bs[KNN];   // descending scores
    int   bi[KNN];
    #pragma unroll
    for (int j = 0; j < KNN; j++) { bs[j] = -3.4e38f; bi[j] = 0; }

    for (int base = 0; base < NPTS; base += KCHUNK) {
        for (int i = tid; i < KCHUNK; i += 128) sp[i] = g_pts4[base + i];
        __syncthreads();
        #pragma unroll 8
        for (int i = 0; i < KCHUNK; i++) {
            float4 p = sp[i];
            float s = fmaf(gx, p.x, fmaf(gy, p.y, fmaf(gz, p.z, -p.w)));
            if (s > bs[KNN - 1]) {
                float cd = s; int ci = base + i;
                #pragma unroll
                for (int j = 0; j < KNN; j++) {
                    if (cd > bs[j]) {
                        float tf = bs[j]; int ti = bi[j];
                        bs[j] = cd; bi[j] = ci; cd = tf; ci = ti;
                    }
                }
            }
        }
        __syncthreads();
    }
    #pragma unroll
    for (int j = 0; j < KNN; j++) g_idx[m * KNN + j] = bi[j];
}

// ---------------- fused edge MLP + mean + out MLP: warp per 2 vertices ----------------
#define SM_EW2 0
#define SM_OW1 4096
#define SM_OW2 14336
#define SM_BUF 18432
#define WBUF 448
#define EDGE_SMEM_FLOATS (SM_BUF + 8 * WBUF)   // 22016 floats = 88064 B

__global__ void __launch_bounds__(256) edge_out_kernel(
    const float* __restrict__ verts, const float* __restrict__ grid,
    const float* __restrict__ gfeat,
    const float* __restrict__ p_ew1,
    const float* __restrict__ p_eg1, const float* __restrict__ p_ebt1,
    const float* __restrict__ p_ew2, const float* __restrict__ p_eb2,
    const float* __restrict__ p_ow1, const float* __restrict__ p_ob1,
    const float* __restrict__ p_og1, const float* __restrict__ p_obt1,
    const float* __restrict__ p_ow2, const float* __restrict__ p_ob2,
    float* __restrict__ out)
{
    extern __shared__ float sm[];
    float* s_ew2 = sm + SM_EW2;
    float* s_ow1 = sm + SM_OW1;
    float* s_ow2 = sm + SM_OW2;

    int tid = threadIdx.x;
    for (int i = tid; i < 1024; i += 256)
        reinterpret_cast<float4*>(s_ew2)[i] = reinterpret_cast<const float4*>(p_ew2)[i];
    for (int i = tid; i < 2560; i += 256)
        reinterpret_cast<float4*>(s_ow1)[i] = reinterpret_cast<const float4*>(p_ow1)[i];
    for (int i = tid; i < 1024; i += 256)
        reinterpret_cast<float4*>(s_ow2)[i] = reinterpret_cast<const float4*>(p_ow2)[i];
    __syncthreads();

    int warp = tid >> 5, lane = tid & 31;
    int c0 = 2 * lane, c1 = c0 + 1;
    int mA = blockIdx.x * 16 + warp * 2, mB = mA + 1;
    float* tA = sm + SM_BUF + warp * WBUF;
    float* tB = tA + 64;
    float* oA = tA + 128;
    float* oB = tA + 288;

    // per-lane weight/affine constants
    float2 wx = *reinterpret_cast<const float2*>(&p_ew1[2048 + c0]);
    float2 wy = *reinterpret_cast<const float2*>(&p_ew1[2112 + c0]);
    float2 wz = *reinterpret_cast<const float2*>(&p_ew1[2176 + c0]);
    float2 eg  = *reinterpret_cast<const float2*>(&p_eg1[c0]);
    float2 ebt = *reinterpret_cast<const float2*>(&p_ebt1[c0]);
    float2 eb2v = *reinterpret_cast<const float2*>(&p_eb2[c0]);
    float2 ob1v = *reinterpret_cast<const float2*>(&p_ob1[c0]);
    float2 ogv  = *reinterpret_cast<const float2*>(&p_og1[c0]);
    float2 obtv = *reinterpret_cast<const float2*>(&p_obt1[c0]);
    float2 ob2v = *reinterpret_cast<const float2*>(&p_ob2[c0]);
    // broadcast LN closed-form constants
    float Wsx = g_wc[0], Wsy = g_wc[1], Wsz = g_wc[2];
    float Mxx = g_wc[3], Myy = g_wc[4], Mzz = g_wc[5];
    float Mxy = g_wc[6], Mxz = g_wc[7], Myz = g_wc[8];

    float gxA = grid[3 * mA], gyA = grid[3 * mA + 1], gzA = grid[3 * mA + 2];
    float gxB = grid[3 * mB], gyB = grid[3 * mB + 1], gzB = grid[3 * mB + 2];

    const int* idxA = g_idx + mA * KNN;
    const int* idxB = g_idx + mB * KNN;
    float accA0 = 0.f, accA1 = 0.f, accB0 = 0.f, accB1 = 0.f;

    #pragma unroll 2
    for (int k = 0; k < KNN; k++) {
        {   // vertex A
            int n = idxA[k];
            float rx = verts[3 * n] - gxA, ry = verts[3 * n + 1] - gyA, rz = verts[3 * n + 2] - gzA;
            float4 sa = g_SA[n]; float t2 = g_T2[n];
            float2 P = g_P[n * 32 + lane];
            float h0 = fmaf(rx, wx.x, fmaf(ry, wy.x, fmaf(rz, wz.x, P.x)));
            float h1 = fmaf(rx, wx.y, fmaf(ry, wy.y, fmaf(rz, wz.y, P.y)));
            float sh = fmaf(rx, Wsx, fmaf(ry, Wsy, fmaf(rz, Wsz, sa.x)));
            float cross = fmaf(rx, sa.z, fmaf(ry, sa.w, rz * t2));
            float q = fmaf(rx * rx, Mxx, fmaf(ry * ry, Myy, rz * rz * Mzz))
                    + 2.f * fmaf(rx * ry, Mxy, fmaf(rx * rz, Mxz, ry * rz * Myz));
            float sh2 = fmaf(2.f, cross, sa.y + q);
            float mean = sh * 0.015625f;
            float var = fmaf(sh2, 0.015625f, -mean * mean);
            float rstd = rsqrtf(var + 1e-5f);
            float y0 = fmaf((h0 - mean) * rstd, eg.x, ebt.x);
            float y1 = fmaf((h1 - mean) * rstd, eg.y, ebt.y);
            accA0 += gelu_tanh(y0); accA1 += gelu_tanh(y1);
        }
        {   // vertex B
            int n = idxB[k];
            float rx = verts[3 * n] - gxB, ry = verts[3 * n + 1] - gyB, rz = verts[3 * n + 2] - gzB;
            float4 sa = g_SA[n]; float t2 = g_T2[n];
            float2 P = g_P[n * 32 + lane];
            float h0 = fmaf(rx, wx.x, fmaf(ry, wy.x, fmaf(rz, wz.x, P.x)));
            float h1 = fmaf(rx, wx.y, fmaf(ry, wy.y, fmaf(rz, wz.y, P.y)));
            float sh = fmaf(rx, Wsx, fmaf(ry, Wsy, fmaf(rz, Wsz, sa.x)));
            float cross = fmaf(rx, sa.z, fmaf(ry, sa.w, rz * t2));
            float q = fmaf(rx * rx, Mxx, fmaf(ry * ry, Myy, rz * rz * Mzz))
                    + 2.f * fmaf(rx * ry, Mxy, fmaf(rx * rz, Mxz, ry * rz * Myz));
            float sh2 = fmaf(2.f, cross, sa.y + q);
            float mean = sh * 0.015625f;
            float var = fmaf(sh2, 0.015625f, -mean * mean);
            float rstd = rsqrtf(var + 1e-5f);
            float y0 = fmaf((h0 - mean) * rstd, eg.x, ebt.x);
            float y1 = fmaf((h1 - mean) * rstd, eg.y, ebt.y);
            accB0 += gelu_tanh(y0); accB1 += gelu_tanh(y1);
        }
    }
    accA0 *= 0.0625f; accA1 *= 0.0625f; accB0 *= 0.0625f; accB1 *= 0.0625f;

    tA[c0] = accA0; tA[c1] = accA1; tB[c0] = accB0; tB[c1] = accB1;
    __syncwarp();
    // agg = mean(gelu) @ ew2 + eb2     (ew2 hoisted out of K-loop by linearity)
    float aA0 = eb2v.x, aA1 = eb2v.y, aB0 = eb2v.x, aB1 = eb2v.y;
    #pragma unroll 8
    for (int j = 0; j < 64; j++) {
        float2 w = *reinterpret_cast<const float2*>(&s_ew2[j * 64 + c0]);
        float gA = tA[j], gB = tB[j];
        aA0 = fmaf(gA, w.x, aA0); aA1 = fmaf(gA, w.y, aA1);
        aB0 = fmaf(gB, w.x, aB0); aB1 = fmaf(gB, w.y, aB1);
    }
    __syncwarp();
    oA[c0] = aA0; oA[c1] = aA1; oB[c0] = aB0; oB[c1] = aB1;
    oA[64 + lane]  = gfeat[mA * 96 + lane];
    oA[96 + lane]  = gfeat[mA * 96 + 32 + lane];
    oA[128 + lane] = gfeat[mA * 96 + 64 + lane];
    oB[64 + lane]  = gfeat[mB * 96 + lane];
    oB[96 + lane]  = gfeat[mB * 96 + 32 + lane];
    oB[128 + lane] = gfeat[mB * 96 + 64 + lane];
    __syncwarp();
    // z = o @ ow1 + ob1
    float zA0 = ob1v.x, zA1 = ob1v.y, zB0 = ob1v.x, zB1 = ob1v.y;
    #pragma unroll 8
    for (int j = 0; j < 160; j++) {
        float2 w = *reinterpret_cast<const float2*>(&s_ow1[j * 64 + c0]);
        float ojA = oA[j], ojB = oB[j];
        zA0 = fmaf(ojA, w.x, zA0); zA1 = fmaf(ojA, w.y, zA1);
        zB0 = fmaf(ojB, w.x, zB0); zB1 = fmaf(ojB, w.y, zB1);
    }
    // LN2 + gelu (warp reductions, once per vertex)
    {
        float meanA = warp_sum(zA0 + zA1) * 0.015625f;
        float meanB = warp_sum(zB0 + zB1) * 0.015625f;
        float dA0 = zA0 - meanA, dA1 = zA1 - meanA;
        float dB0 = zB0 - meanB, dB1 = zB1 - meanB;
        float varA = warp_sum(fmaf(dA0, dA0, dA1 * dA1)) * 0.015625f;
        float varB = warp_sum(fmaf(dB0, dB0, dB1 * dB1)) * 0.015625f;
        float rsA = rsqrtf(varA + 1e-5f), rsB = rsqrtf(varB + 1e-5f);
        zA0 = gelu_tanh(fmaf(dA0 * rsA, ogv.x, obtv.x));
        zA1 = gelu_tanh(fmaf(dA1 * rsA, ogv.y, obtv.y));
        zB0 = gelu_tanh(fmaf(dB0 * rsB, ogv.x, obtv.x));
        zB1 = gelu_tanh(fmaf(dB1 * rsB, ogv.y, obtv.y));
    }
    __syncwarp();
    tA[c0] = zA0; tA[c1] = zA1; tB[c0] = zB0; tB[c1] = zB1;
    __syncwarp();
    // out = y @ ow2 + ob2
    float fA0 = ob2v.x, fA1 = ob2v.y, fB0 = ob2v.x, fB1 = ob2v.y;
    #pragma unroll 8
    for (int j = 0; j < 64; j++) {
        float2 w = *reinterpret_cast<const float2*>(&s_ow2[j * 64 + c0]);
        float yA = tA[j], yB = tB[j];
        fA0 = fmaf(yA, w.x, fA0); fA1 = fmaf(yA, w.y, fA1);
        fB0 = fmaf(yB, w.x, fB0); fB1 = fmaf(yB, w.y, fB1);
    }
    *reinterpret_cast<float2*>(&out[mA * 64 + c0]) = make_float2(fA0, fA1);
    *reinterpret_cast<float2*>(&out[mB * 64 + c0]) = make_float2(fB0, fB1);
}

// ---------------- launch ----------------
extern "C" void kernel_launch(void* const* d_in, const int* in_sizes, int n_in,
                              void* d_out, int out_size) {
    const float* verts = (const float*)d_in[0];
    const float* feat  = (const float*)d_in[1];
    const float* grid  = (const float*)d_in[2];
    const float* gfeat = (const float*)d_in[3];
    const float* ew1   = (const float*)d_in[4];
    const float* eb1   = (const float*)d_in[5];
    const float* eg1   = (const float*)d_in[6];
    const float* ebt1  = (const float*)d_in[7];
    const float* ew2   = (const float*)d_in[8];
    const float* eb2   = (const float*)d_in[9];
    const float* ow1   = (const float*)d_in[10];
    const float* ob1   = (const float*)d_in[11];
    const float* og1   = (const float*)d_in[12];
    const float* obt1  = (const float*)d_in[13];
    const float* ow2   = (const float*)d_in[14];
    const float* ob2   = (const float*)d_in[15];
    float* out = (float*)d_out;

    prep_pts_kernel<<<32, 256>>>(verts);
    prep_const_kernel<<<1, 32>>>(ew1);
    prep_P_kernel<<<1024, 256>>>(feat, ew1, eb1);
    knn_kernel<<<NGRID / 128, 128>>>(grid);

    int smem = EDGE_SMEM_FLOATS * (int)sizeof(float);
    cudaFuncSetAttribute(edge_out_kernel, cudaFuncAttributeMaxDynamicSharedMemorySize, smem);
    edge_out_kernel<<<NGRID / 16, 256, smem>>>(verts, grid, gfeat,
                                               ew1, eg1, ebt1, ew2, eb2,
                                               ow1, ob1, og1, obt1, ow2, ob2, out);
}